// round 8
// baseline (speedup 1.0000x reference)
#include <cuda_runtime.h>

#define NROWS 1024
#define EMB   256
#define WIN   384   // bounds window (multiple of 128); always covers a group

// Grid: 2*NROWS row CTAs (128 thr) + 1 count CTA.
// Row CTA (bid < 2048): i = bid>>1, ch = bid&1.
//   - per-warp windowed count around i -> [lo,hi)   (no barrier anywhere)
//   - zero phase: thread t owns cols [ch*512 + t*4, +4): one float4 per array,
//     skipped/partial where it overlaps [lo,hi)
//   - compute: half-warp-per-j (16 lanes x 16 dims), 16 streams/row, 2-way
//     unrolled, 4-step shfl reduce; interior cols all written (diag = 0).
// Count CTA (bid == 2048): 32-bin histogram; count = sum h^2 - N.
__global__ __launch_bounds__(128) void distmax_all(
    const float* __restrict__ xs, const int* __restrict__ batch,
    const float* __restrict__ w, const float* __restrict__ bptr,
    float* __restrict__ out_pred, float* __restrict__ out_mask,
    float* __restrict__ out_count)
{
    const int t    = threadIdx.x;
    const int lane = t & 31;
    const int wid  = t >> 5;
    const int bid  = blockIdx.x;

    // ---- count CTA ----
    if (bid == 2 * NROWS) {
        __shared__ int h[32];
        if (t < 32) h[t] = 0;
        __syncthreads();
        #pragma unroll
        for (int k = 0; k < 2; k++) {
            int4 v = reinterpret_cast<const int4*>(batch)[t + k * 128];
            atomicAdd(&h[v.x], 1);
            atomicAdd(&h[v.y], 1);
            atomicAdd(&h[v.z], 1);
            atomicAdd(&h[v.w], 1);
        }
        __syncthreads();
        if (t < 32) {
            int c = h[t] * h[t];
            #pragma unroll
            for (int o = 16; o; o >>= 1) c += __shfl_xor_sync(0xffffffffu, c, o);
            if (t == 0) out_count[0] = (float)(c - NROWS);
        }
        return;
    }

    const int i  = bid >> 1;
    const int ch = bid & 1;

    // ---- windowed bounds (each warp independently) ----
    int wbase = i - WIN / 2;
    if (wbase < 0) wbase = 0;
    wbase &= ~3;
    if (wbase > NROWS - WIN) wbase = NROWS - WIN;

    const int bi = __ldg(batch + i);
    int nbefore = 0, nafter = 0;
    const int4* b4 = reinterpret_cast<const int4*>(batch + wbase);
    #pragma unroll
    for (int k = 0; k < WIN / 128; k++) {
        const int4 v = b4[k * 32 + lane];
        const int g0 = wbase + (k * 32 + lane) * 4;
        nbefore += (v.x == bi && g0     < i) + (v.y == bi && g0 + 1 < i)
                 + (v.z == bi && g0 + 2 < i) + (v.w == bi && g0 + 3 < i);
        nafter  += (v.x == bi && g0     > i) + (v.y == bi && g0 + 1 > i)
                 + (v.z == bi && g0 + 2 > i) + (v.w == bi && g0 + 3 > i);
    }
    #pragma unroll
    for (int o = 16; o; o >>= 1) {
        nbefore += __shfl_xor_sync(0xffffffffu, nbefore, o);
        nafter  += __shfl_xor_sync(0xffffffffu, nafter,  o);
    }
    const int lo = i - nbefore;
    const int hi = i + nafter + 1;

    const size_t rowoff = (size_t)i * NROWS;
    float* __restrict__ prow = out_pred + rowoff;
    float* __restrict__ mrow = out_mask + rowoff;

    // ---- zero phase: this half-CTA covers cols [ch*512, ch*512+512) ----
    {
        const int c0 = ch * 512 + t * 4;
        if (c0 + 4 <= lo || c0 >= hi) {
            const float4 z = make_float4(0.f, 0.f, 0.f, 0.f);
            reinterpret_cast<float4*>(prow)[c0 >> 2] = z;
            reinterpret_cast<float4*>(mrow)[c0 >> 2] = z;
        } else if (c0 < lo || c0 + 4 > hi) {
            #pragma unroll
            for (int e = 0; e < 4; e++) {
                const int c = c0 + e;
                if (c < lo || c >= hi) { prow[c] = 0.f; mrow[c] = 0.f; }
            }
        }
    }

    // ---- compute: half-warp-per-j, 16 streams/row, 2-way unrolled ----
    const float bias = __ldg(bptr);
    const int sub = lane & 15;          // sublane within half-warp
    const int hh  = lane >> 4;          // which half
    const int s4  = sub * 4;            // float4 index base: dims [sub*16, +16)

    const float4* xi4 = reinterpret_cast<const float4*>(xs + (size_t)i * EMB);
    const float4* w4  = reinterpret_cast<const float4*>(w);
    const float4 xiA = xi4[s4 + 0], xiB = xi4[s4 + 1], xiC = xi4[s4 + 2], xiD = xi4[s4 + 3];
    const float4 wA  = w4 [s4 + 0], wB  = w4 [s4 + 1], wC  = w4 [s4 + 2], wD  = w4 [s4 + 3];

    const int stream = ch * 8 + wid * 2 + hh;   // 0..15

    for (int j0 = lo + stream; j0 < hi; j0 += 32) {
        const int  j1 = j0 + 16;
        const bool p1 = (j1 < hi);

        float acc0, acc1 = 0.f;
        {
            const float4* xj = reinterpret_cast<const float4*>(xs + (size_t)j0 * EMB);
            const float4 a = xj[s4 + 0], b = xj[s4 + 1], c = xj[s4 + 2], d = xj[s4 + 3];
            acc0 = fmaf(fmaxf(xiA.x, a.x), wA.x,
                   fmaf(fmaxf(xiA.y, a.y), wA.y,
                   fmaf(fmaxf(xiA.z, a.z), wA.z,
                   fmaf(fmaxf(xiA.w, a.w), wA.w,
                   fmaf(fmaxf(xiB.x, b.x), wB.x,
                   fmaf(fmaxf(xiB.y, b.y), wB.y,
                   fmaf(fmaxf(xiB.z, b.z), wB.z,
                   fmaf(fmaxf(xiB.w, b.w), wB.w,
                   fmaf(fmaxf(xiC.x, c.x), wC.x,
                   fmaf(fmaxf(xiC.y, c.y), wC.y,
                   fmaf(fmaxf(xiC.z, c.z), wC.z,
                   fmaf(fmaxf(xiC.w, c.w), wC.w,
                   fmaf(fmaxf(xiD.x, d.x), wD.x,
                   fmaf(fmaxf(xiD.y, d.y), wD.y,
                   fmaf(fmaxf(xiD.z, d.z), wD.z,
                        fmaxf(xiD.w, d.w) * wD.w)))))))))))))));
        }
        if (p1) {
            const float4* xj = reinterpret_cast<const float4*>(xs + (size_t)j1 * EMB);
            const float4 a = xj[s4 + 0], b = xj[s4 + 1], c = xj[s4 + 2], d = xj[s4 + 3];
            acc1 = fmaf(fmaxf(xiA.x, a.x), wA.x,
                   fmaf(fmaxf(xiA.y, a.y), wA.y,
                   fmaf(fmaxf(xiA.z, a.z), wA.z,
                   fmaf(fmaxf(xiA.w, a.w), wA.w,
                   fmaf(fmaxf(xiB.x, b.x), wB.x,
                   fmaf(fmaxf(xiB.y, b.y), wB.y,
                   fmaf(fmaxf(xiB.z, b.z), wB.z,
                   fmaf(fmaxf(xiB.w, b.w), wB.w,
                   fmaf(fmaxf(xiC.x, c.x), wC.x,
                   fmaf(fmaxf(xiC.y, c.y), wC.y,
                   fmaf(fmaxf(xiC.z, c.z), wC.z,
                   fmaf(fmaxf(xiC.w, c.w), wC.w,
                   fmaf(fmaxf(xiD.x, d.x), wD.x,
                   fmaf(fmaxf(xiD.y, d.y), wD.y,
                   fmaf(fmaxf(xiD.z, d.z), wD.z,
                        fmaxf(xiD.w, d.w) * wD.w)))))))))))))));
        }

        // 4-step reduce within each 16-lane half
        #pragma unroll
        for (int o = 8; o; o >>= 1) {
            acc0 += __shfl_xor_sync(0xffffffffu, acc0, o);
            acc1 += __shfl_xor_sync(0xffffffffu, acc1, o);
        }

        if (sub == 0) {
            prow[j0] = (j0 == i) ? 0.f : fmaxf(acc0 + bias, 0.f);
            mrow[j0] = (j0 == i) ? 0.f : 1.f;
            if (p1) {
                prow[j1] = (j1 == i) ? 0.f : fmaxf(acc1 + bias, 0.f);
                mrow[j1] = (j1 == i) ? 0.f : 1.f;
            }
        }
    }
}

extern "C" void kernel_launch(void* const* d_in, const int* in_sizes, int n_in,
                              void* d_out, int out_size)
{
    const float* xs    = (const float*)d_in[0];  // [1024, 256] f32
    const int*   batch = (const int*)d_in[1];    // [1024] int32 (sorted, ids in [0,32))
    const float* w     = (const float*)d_in[2];  // [256] f32
    const float* b     = (const float*)d_in[3];  // [1] f32

    float* out       = (float*)d_out;
    float* out_pred  = out;                              // [1024*1024]
    float* out_mask  = out + (size_t)NROWS * NROWS;      // [1024*1024]
    float* out_count = out + 2 * (size_t)NROWS * NROWS;  // [1]

    distmax_all<<<2 * NROWS + 1, 128>>>(xs, batch, w, b, out_pred, out_mask, out_count);
}

// round 9
// speedup vs baseline: 1.5761x; 1.5761x over previous
#include <cuda_runtime.h>

#define NROWS 1024
#define EMB   256
#define WIN   384   // bounds window (multiple of 128); always covers a group

// Grid: 2*NROWS row CTAs (128 thr) + 1 count CTA.
// Row CTA (bid < 2048): i = bid>>1, ch = bid&1.
//   - per-warp windowed count around i -> [lo,hi)   (no barriers anywhere)
//   - zero phase: this half-CTA covers cols [ch*512, ch*512+512), one
//     float4 per thread per array, partial where it overlaps [lo,hi)
//   - compute: FULL-warp-per-j, perfectly coalesced (lane reads float4
//     [lane] and [32+lane] of each row), 4-way unrolled, 5-step shfl.
// Count CTA (bid == 2048): 32-bin histogram; count = sum h^2 - N.
__global__ __launch_bounds__(128) void distmax_all(
    const float* __restrict__ xs, const int* __restrict__ batch,
    const float* __restrict__ w, const float* __restrict__ bptr,
    float* __restrict__ out_pred, float* __restrict__ out_mask,
    float* __restrict__ out_count)
{
    const int t    = threadIdx.x;
    const int lane = t & 31;
    const int wid  = t >> 5;
    const int bid  = blockIdx.x;

    // ---- count CTA ----
    if (bid == 2 * NROWS) {
        __shared__ int h[32];
        if (t < 32) h[t] = 0;
        __syncthreads();
        #pragma unroll
        for (int k = 0; k < 2; k++) {
            int4 v = reinterpret_cast<const int4*>(batch)[t + k * 128];
            atomicAdd(&h[v.x], 1);
            atomicAdd(&h[v.y], 1);
            atomicAdd(&h[v.z], 1);
            atomicAdd(&h[v.w], 1);
        }
        __syncthreads();
        if (t < 32) {
            int c = h[t] * h[t];
            #pragma unroll
            for (int o = 16; o; o >>= 1) c += __shfl_xor_sync(0xffffffffu, c, o);
            if (t == 0) out_count[0] = (float)(c - NROWS);
        }
        return;
    }

    const int i  = bid >> 1;
    const int ch = bid & 1;

    // ---- windowed bounds (each warp independently) ----
    int wbase = i - WIN / 2;
    if (wbase < 0) wbase = 0;
    wbase &= ~3;
    if (wbase > NROWS - WIN) wbase = NROWS - WIN;

    const int bi = __ldg(batch + i);
    int nbefore = 0, nafter = 0;
    const int4* b4 = reinterpret_cast<const int4*>(batch + wbase);
    #pragma unroll
    for (int k = 0; k < WIN / 128; k++) {
        const int4 v = b4[k * 32 + lane];
        const int g0 = wbase + (k * 32 + lane) * 4;
        nbefore += (v.x == bi && g0     < i) + (v.y == bi && g0 + 1 < i)
                 + (v.z == bi && g0 + 2 < i) + (v.w == bi && g0 + 3 < i);
        nafter  += (v.x == bi && g0     > i) + (v.y == bi && g0 + 1 > i)
                 + (v.z == bi && g0 + 2 > i) + (v.w == bi && g0 + 3 > i);
    }
    #pragma unroll
    for (int o = 16; o; o >>= 1) {
        nbefore += __shfl_xor_sync(0xffffffffu, nbefore, o);
        nafter  += __shfl_xor_sync(0xffffffffu, nafter,  o);
    }
    const int lo = i - nbefore;
    const int hi = i + nafter + 1;

    const size_t rowoff = (size_t)i * NROWS;
    float* __restrict__ prow = out_pred + rowoff;
    float* __restrict__ mrow = out_mask + rowoff;

    // ---- zero phase: this half-CTA covers cols [ch*512, ch*512+512) ----
    {
        const int c0 = ch * 512 + t * 4;
        if (c0 + 4 <= lo || c0 >= hi) {
            const float4 z = make_float4(0.f, 0.f, 0.f, 0.f);
            reinterpret_cast<float4*>(prow)[c0 >> 2] = z;
            reinterpret_cast<float4*>(mrow)[c0 >> 2] = z;
        } else if (c0 < lo || c0 + 4 > hi) {
            #pragma unroll
            for (int e = 0; e < 4; e++) {
                const int c = c0 + e;
                if (c < lo || c >= hi) { prow[c] = 0.f; mrow[c] = 0.f; }
            }
        }
    }

    // ---- compute: full-warp-per-j, coalesced, 4-way unrolled ----
    // Lane owns dims [4*lane, 4*lane+4) and [128+4*lane, 128+4*lane+4):
    // float4 indices lane and 32+lane -> each LDG.128 is lane-contiguous.
    const float bias = __ldg(bptr);
    const float4* xi4 = reinterpret_cast<const float4*>(xs + (size_t)i * EMB);
    const float4* w4  = reinterpret_cast<const float4*>(w);
    const float4 xi0 = xi4[lane], xi1 = xi4[32 + lane];
    const float4 w0  = w4 [lane], w1  = w4 [32 + lane];

    const int stream = ch * 4 + wid;   // 0..7

    for (int jb = lo + stream; jb < hi; jb += 32) {
        const int j0 = jb, j1 = jb + 8, j2 = jb + 16, j3 = jb + 24;
        const bool p1 = (j1 < hi), p2 = (j2 < hi), p3 = (j3 < hi);

        float acc0 = 0.f, acc1 = 0.f, acc2 = 0.f, acc3 = 0.f;
        {
            const float4* xj = reinterpret_cast<const float4*>(xs + (size_t)j0 * EMB);
            const float4 a = xj[lane], b = xj[32 + lane];
            acc0 = fmaf(fmaxf(xi0.x, a.x), w0.x,
                   fmaf(fmaxf(xi0.y, a.y), w0.y,
                   fmaf(fmaxf(xi0.z, a.z), w0.z,
                   fmaf(fmaxf(xi0.w, a.w), w0.w,
                   fmaf(fmaxf(xi1.x, b.x), w1.x,
                   fmaf(fmaxf(xi1.y, b.y), w1.y,
                   fmaf(fmaxf(xi1.z, b.z), w1.z,
                        fmaxf(xi1.w, b.w) * w1.w)))))));
        }
        if (p1) {
            const float4* xj = reinterpret_cast<const float4*>(xs + (size_t)j1 * EMB);
            const float4 a = xj[lane], b = xj[32 + lane];
            acc1 = fmaf(fmaxf(xi0.x, a.x), w0.x,
                   fmaf(fmaxf(xi0.y, a.y), w0.y,
                   fmaf(fmaxf(xi0.z, a.z), w0.z,
                   fmaf(fmaxf(xi0.w, a.w), w0.w,
                   fmaf(fmaxf(xi1.x, b.x), w1.x,
                   fmaf(fmaxf(xi1.y, b.y), w1.y,
                   fmaf(fmaxf(xi1.z, b.z), w1.z,
                        fmaxf(xi1.w, b.w) * w1.w)))))));
        }
        if (p2) {
            const float4* xj = reinterpret_cast<const float4*>(xs + (size_t)j2 * EMB);
            const float4 a = xj[lane], b = xj[32 + lane];
            acc2 = fmaf(fmaxf(xi0.x, a.x), w0.x,
                   fmaf(fmaxf(xi0.y, a.y), w0.y,
                   fmaf(fmaxf(xi0.z, a.z), w0.z,
                   fmaf(fmaxf(xi0.w, a.w), w0.w,
                   fmaf(fmaxf(xi1.x, b.x), w1.x,
                   fmaf(fmaxf(xi1.y, b.y), w1.y,
                   fmaf(fmaxf(xi1.z, b.z), w1.z,
                        fmaxf(xi1.w, b.w) * w1.w)))))));
        }
        if (p3) {
            const float4* xj = reinterpret_cast<const float4*>(xs + (size_t)j3 * EMB);
            const float4 a = xj[lane], b = xj[32 + lane];
            acc3 = fmaf(fmaxf(xi0.x, a.x), w0.x,
                   fmaf(fmaxf(xi0.y, a.y), w0.y,
                   fmaf(fmaxf(xi0.z, a.z), w0.z,
                   fmaf(fmaxf(xi0.w, a.w), w0.w,
                   fmaf(fmaxf(xi1.x, b.x), w1.x,
                   fmaf(fmaxf(xi1.y, b.y), w1.y,
                   fmaf(fmaxf(xi1.z, b.z), w1.z,
                        fmaxf(xi1.w, b.w) * w1.w)))))));
        }

        #pragma unroll
        for (int o = 16; o; o >>= 1) {
            acc0 += __shfl_xor_sync(0xffffffffu, acc0, o);
            acc1 += __shfl_xor_sync(0xffffffffu, acc1, o);
            acc2 += __shfl_xor_sync(0xffffffffu, acc2, o);
            acc3 += __shfl_xor_sync(0xffffffffu, acc3, o);
        }

        if (lane == 0) {
            prow[j0] = (j0 == i) ? 0.f : fmaxf(acc0 + bias, 0.f);
            mrow[j0] = (j0 == i) ? 0.f : 1.f;
            if (p1) { prow[j1] = (j1 == i) ? 0.f : fmaxf(acc1 + bias, 0.f);
                      mrow[j1] = (j1 == i) ? 0.f : 1.f; }
            if (p2) { prow[j2] = (j2 == i) ? 0.f : fmaxf(acc2 + bias, 0.f);
                      mrow[j2] = (j2 == i) ? 0.f : 1.f; }
            if (p3) { prow[j3] = (j3 == i) ? 0.f : fmaxf(acc3 + bias, 0.f);
                      mrow[j3] = (j3 == i) ? 0.f : 1.f; }
        }
    }
}

extern "C" void kernel_launch(void* const* d_in, const int* in_sizes, int n_in,
                              void* d_out, int out_size)
{
    const float* xs    = (const float*)d_in[0];  // [1024, 256] f32
    const int*   batch = (const int*)d_in[1];    // [1024] int32 (sorted, ids in [0,32))
    const float* w     = (const float*)d_in[2];  // [256] f32
    const float* b     = (const float*)d_in[3];  // [1] f32

    float* out       = (float*)d_out;
    float* out_pred  = out;                              // [1024*1024]
    float* out_mask  = out + (size_t)NROWS * NROWS;      // [1024*1024]
    float* out_count = out + 2 * (size_t)NROWS * NROWS;  // [1]

    distmax_all<<<2 * NROWS + 1, 128>>>(xs, batch, w, b, out_pred, out_mask, out_count);
}